// round 7
// baseline (speedup 1.0000x reference)
#include <cuda_runtime.h>

// Problem constants (fixed shapes)
#define DX 256
#define DY 256
#define DZ 32
#define DT 5
#define CIN 8
#define COUT 8
#define NVOX 10485760            // DT*DZ*DY*DX
#define MASK_WORDS 327680        // NVOX / 32
#define LIST_CAP 131072

// Scratch: __device__ globals (no allocation allowed)
__device__ unsigned g_mask[MASK_WORDS];
__device__ unsigned g_list[LIST_CAP];
__device__ unsigned g_count;
__device__ float    g_wsum[81 * 8];

// ---------------------------------------------------------------------------
// K0: clear bitmask + counter, precompute Wsum[k][f] = sum_c W[k][c][f]
// ---------------------------------------------------------------------------
__global__ void k_init(const float* __restrict__ W) {
    int i = blockIdx.x * blockDim.x + threadIdx.x;
    if (i < MASK_WORDS) g_mask[i] = 0u;
    if (i == 0) g_count = 0u;
    if (i < 81 * 8) {
        int k = i >> 3, f = i & 7;
        float s = 0.f;
#pragma unroll
        for (int c = 0; c < CIN; ++c) s += W[k * (CIN * COUT) + c * COUT + f];
        g_wsum[i] = s;
    }
}

// ---------------------------------------------------------------------------
// K1: quantize points -> voxel ids, set occupancy bit, append unique vids
// Bit-match XLA: divide-by-const is simplified to multiply-by-reciprocal,
// and 1/0.2f rounds to exactly 5.0f. So q = (p - offset) * 5.0f.
// ---------------------------------------------------------------------------
__global__ void k_points(const float4* __restrict__ pts, int n) {
    int i = blockIdx.x * blockDim.x + threadIdx.x;
    if (i >= n) return;
    float4 p = pts[i];
    int ix = (int)floorf(__fmul_rn(__fadd_rn(p.x, 25.6f), 5.0f));
    int iy = (int)floorf(__fmul_rn(__fadd_rn(p.y, 25.6f), 5.0f));
    int iz = (int)floorf(__fmul_rn(__fadd_rn(p.z, 3.2f),  5.0f));
    int it = (int)floorf(p.w);
    ix = min(max(ix, 0), DX - 1);
    iy = min(max(iy, 0), DY - 1);
    iz = min(max(iz, 0), DZ - 1);
    it = min(max(it, 0), DT - 1);
    unsigned vid = (((unsigned)it * DZ + (unsigned)iz) * DY + (unsigned)iy) * DX + (unsigned)ix;
    unsigned bit = 1u << (vid & 31u);
    unsigned old = atomicOr(&g_mask[vid >> 5], bit);
    if (!(old & bit)) {
        unsigned pos = atomicAdd(&g_count, 1u);
        if (pos < LIST_CAP) g_list[pos] = vid;
    }
}

// ---------------------------------------------------------------------------
// K2: zero-fill dense output (335.5 MB), grid-stride 128-bit stores
// ---------------------------------------------------------------------------
__global__ void k_zero(uint4* __restrict__ out, int n4) {
    int stride = gridDim.x * blockDim.x;
    for (int i = blockIdx.x * blockDim.x + threadIdx.x; i < n4; i += stride)
        out[i] = make_uint4(0u, 0u, 0u, 0u);
}

// ---------------------------------------------------------------------------
// K3: one thread per active voxel; 81 occupancy probes feed 8 channel
//     accumulators in registers. out[f] = relu( sum_k m_k * Wsum[k][f] ).
// ---------------------------------------------------------------------------
__global__ void k_conv(float* __restrict__ out) {
    __shared__ float s_wsum[81 * 8];
    for (int i = threadIdx.x; i < 81 * 8; i += blockDim.x) s_wsum[i] = g_wsum[i];
    __syncthreads();

    int vi = blockIdx.x * blockDim.x + threadIdx.x;
    unsigned cnt = g_count;
    if (cnt > LIST_CAP) cnt = LIST_CAP;
    if ((unsigned)vi >= cnt) return;

    unsigned vid = g_list[vi];
    int x = vid & 255;
    int y = (vid >> 8) & 255;
    int z = (vid >> 16) & 31;
    int t = vid >> 21;

    float acc[COUT];
#pragma unroll
    for (int f = 0; f < COUT; ++f) acc[f] = 0.f;

#pragma unroll
    for (int k = 0; k < 81; ++k) {
        const int dx = k / 27 - 1;
        const int dy = (k / 9) % 3 - 1;
        const int dz = (k / 3) % 3 - 1;
        const int dt = k % 3 - 1;
        bool inb = ((unsigned)(x + dx) < (unsigned)DX) &
                   ((unsigned)(y + dy) < (unsigned)DY) &
                   ((unsigned)(z + dz) < (unsigned)DZ) &
                   ((unsigned)(t + dt) < (unsigned)DT);
        bool on = false;
        if (inb) {
            int nid = (int)vid + (dt * (DZ * DY * DX) + dz * (DY * DX) + dy * DX + dx);
            unsigned w = g_mask[(unsigned)nid >> 5];
            on = (w >> ((unsigned)nid & 31u)) & 1u;
        }
        if (on) {
#pragma unroll
            for (int f = 0; f < COUT; ++f) acc[f] += s_wsum[k * 8 + f];
        }
    }
#pragma unroll
    for (int f = 0; f < COUT; ++f)
        out[(unsigned)f * (unsigned)NVOX + vid] = fmaxf(acc[f], 0.f);
}

// ---------------------------------------------------------------------------
extern "C" void kernel_launch(void* const* d_in, const int* in_sizes, int n_in,
                              void* d_out, int out_size) {
    const float4* pts = (const float4*)d_in[0];
    const float*  W   = (const float*)d_in[1];
    float* out = (float*)d_out;
    int n = in_sizes[0] / 4;

    // k_zero first: the 335 MB store stream overlaps the tiny init/points
    // kernels on the same stream's tail (no dependency between them).
    int n4 = out_size / 4;                       // 20.97M uint4
    k_zero<<<148 * 8, 256>>>((uint4*)d_out, n4); // grid-stride, full-chip

    k_init<<<(MASK_WORDS + 255) / 256, 256>>>(W);
    k_points<<<(n + 255) / 256, 256>>>(pts, n);

    k_conv<<<(n + 255) / 256, 256>>>(out);       // n threads >= active voxel count
}

// round 8
// speedup vs baseline: 1.1128x; 1.1128x over previous
#include <cuda_runtime.h>

// Problem constants (fixed shapes)
#define DX 256
#define DY 256
#define DZ 32
#define DT 5
#define CIN 8
#define COUT 8
#define NVOX 10485760            // DT*DZ*DY*DX
#define MASK_WORDS 327680        // NVOX / 32
#define MASK_QWORDS 163840       // NVOX / 64
#define LIST_CAP 131072

// Scratch: __device__ globals (no allocation allowed)
__device__ unsigned long long g_mask64[MASK_QWORDS];
__device__ unsigned g_list[LIST_CAP];
__device__ unsigned g_count;
__device__ float    g_wsum[81 * 8];

// ---------------------------------------------------------------------------
// K0: clear bitmask + counter, precompute Wsum[k][f] = sum_c W[k][c][f]
// ---------------------------------------------------------------------------
__global__ void k_init(const float* __restrict__ W) {
    int i = blockIdx.x * blockDim.x + threadIdx.x;
    if (i < MASK_QWORDS) g_mask64[i] = 0ull;
    if (i == 0) g_count = 0u;
    if (i < 81 * 8) {
        int k = i >> 3, f = i & 7;
        float s = 0.f;
#pragma unroll
        for (int c = 0; c < CIN; ++c) s += W[k * (CIN * COUT) + c * COUT + f];
        g_wsum[i] = s;
    }
}

// ---------------------------------------------------------------------------
// K1: quantize points -> voxel ids, set occupancy bit, append unique vids
// Bit-match XLA: /0.2f is folded to *5.0f (reciprocal rounds exactly).
// ---------------------------------------------------------------------------
__global__ void k_points(const float4* __restrict__ pts, int n) {
    int i = blockIdx.x * blockDim.x + threadIdx.x;
    if (i >= n) return;
    float4 p = pts[i];
    int ix = (int)floorf(__fmul_rn(__fadd_rn(p.x, 25.6f), 5.0f));
    int iy = (int)floorf(__fmul_rn(__fadd_rn(p.y, 25.6f), 5.0f));
    int iz = (int)floorf(__fmul_rn(__fadd_rn(p.z, 3.2f),  5.0f));
    int it = (int)floorf(p.w);
    ix = min(max(ix, 0), DX - 1);
    iy = min(max(iy, 0), DY - 1);
    iz = min(max(iz, 0), DZ - 1);
    it = min(max(it, 0), DT - 1);
    unsigned vid = (((unsigned)it * DZ + (unsigned)iz) * DY + (unsigned)iy) * DX + (unsigned)ix;
    unsigned* mask32 = (unsigned*)g_mask64;
    unsigned bit = 1u << (vid & 31u);
    unsigned old = atomicOr(&mask32[vid >> 5], bit);
    if (!(old & bit)) {
        unsigned pos = atomicAdd(&g_count, 1u);
        if (pos < LIST_CAP) g_list[pos] = vid;
    }
}

// ---------------------------------------------------------------------------
// K2: zero-fill dense output (335.5 MB), grid-stride 128-bit stores
// ---------------------------------------------------------------------------
__global__ void k_zero(uint4* __restrict__ out, int n4) {
    int stride = gridDim.x * blockDim.x;
    for (int i = blockIdx.x * blockDim.x + threadIdx.x; i < n4; i += stride)
        out[i] = make_uint4(0u, 0u, 0u, 0u);
}

// ---------------------------------------------------------------------------
// K3: one thread per active voxel. For each of 27 (dy,dz,dt) rows, ONE u64
// mask load yields the 3 x-neighbor bits (dx=-1,0,+1). 8 channel accs in regs.
// k index layout: k = (dx+1)*27 + (dy+1)*9 + (dz+1)*3 + (dt+1).
// ---------------------------------------------------------------------------
__global__ void k_conv(float* __restrict__ out) {
    __shared__ float4 s_wsum4[81 * 2];   // [k][f0..3],[f4..7]
    for (int i = threadIdx.x; i < 81 * 2; i += blockDim.x)
        s_wsum4[i] = ((const float4*)g_wsum)[i];
    __syncthreads();

    int vi = blockIdx.x * blockDim.x + threadIdx.x;
    unsigned cnt = g_count;
    if (cnt > LIST_CAP) cnt = LIST_CAP;
    if ((unsigned)vi >= cnt) return;

    unsigned vid = g_list[vi];
    int x = vid & 255;
    int y = (vid >> 8) & 255;
    int z = (vid >> 16) & 31;
    int t = vid >> 21;

    float4 acc0 = make_float4(0.f, 0.f, 0.f, 0.f);
    float4 acc1 = make_float4(0.f, 0.f, 0.f, 0.f);

    // x-boundary bit masks (dx=-1 invalid at x==0, dx=+1 invalid at x==255)
    unsigned xmask = 7u;
    if (x == 0)      xmask &= ~1u;
    if (x == DX - 1) xmask &= ~4u;

#pragma unroll
    for (int dy = -1; dy <= 1; ++dy) {
        bool vy = ((unsigned)(y + dy) < (unsigned)DY);
#pragma unroll
        for (int dz = -1; dz <= 1; ++dz) {
            bool vz = ((unsigned)(z + dz) < (unsigned)DZ);
#pragma unroll
            for (int dt = -1; dt <= 1; ++dt) {
                bool vt = ((unsigned)(t + dt) < (unsigned)DT);
                if (vy & vz & vt) {
                    int base = (int)vid + dt * (DZ * DY * DX) + dz * (DY * DX) + dy * DX;
                    unsigned bpos = (unsigned)base & 63u;
                    unsigned widx = (unsigned)base >> 6;
                    unsigned long long w = g_mask64[widx];
                    unsigned m;
                    if (bpos >= 1u && bpos <= 62u) {
                        m = (unsigned)((w >> (bpos - 1u)) & 7ull);
                    } else if (bpos == 0u) {
                        unsigned long long lo = (widx > 0u) ? g_mask64[widx - 1u] : 0ull;
                        m = (unsigned)((lo >> 63) | ((w & 3ull) << 1));
                    } else { // bpos == 63
                        unsigned long long hi = (widx + 1u < MASK_QWORDS) ? g_mask64[widx + 1u] : 0ull;
                        m = (unsigned)(((w >> 62) & 3ull) | ((hi & 1ull) << 2));
                    }
                    m &= xmask;
                    if (m) {
                        int k0 = (dy + 1) * 9 + (dz + 1) * 3 + (dt + 1);
                        if (m & 1u) {   // dx = -1 -> k0
                            float4 a = s_wsum4[k0 * 2], b = s_wsum4[k0 * 2 + 1];
                            acc0.x += a.x; acc0.y += a.y; acc0.z += a.z; acc0.w += a.w;
                            acc1.x += b.x; acc1.y += b.y; acc1.z += b.z; acc1.w += b.w;
                        }
                        if (m & 2u) {   // dx = 0 -> k0 + 27
                            int kk = k0 + 27;
                            float4 a = s_wsum4[kk * 2], b = s_wsum4[kk * 2 + 1];
                            acc0.x += a.x; acc0.y += a.y; acc0.z += a.z; acc0.w += a.w;
                            acc1.x += b.x; acc1.y += b.y; acc1.z += b.z; acc1.w += b.w;
                        }
                        if (m & 4u) {   // dx = +1 -> k0 + 54
                            int kk = k0 + 54;
                            float4 a = s_wsum4[kk * 2], b = s_wsum4[kk * 2 + 1];
                            acc0.x += a.x; acc0.y += a.y; acc0.z += a.z; acc0.w += a.w;
                            acc1.x += b.x; acc1.y += b.y; acc1.z += b.z; acc1.w += b.w;
                        }
                    }
                }
            }
        }
    }

    out[0u * NVOX + vid] = fmaxf(acc0.x, 0.f);
    out[1u * NVOX + vid] = fmaxf(acc0.y, 0.f);
    out[2u * NVOX + vid] = fmaxf(acc0.z, 0.f);
    out[3u * NVOX + vid] = fmaxf(acc0.w, 0.f);
    out[4u * NVOX + vid] = fmaxf(acc1.x, 0.f);
    out[5u * NVOX + vid] = fmaxf(acc1.y, 0.f);
    out[6u * NVOX + vid] = fmaxf(acc1.z, 0.f);
    out[7u * NVOX + vid] = fmaxf(acc1.w, 0.f);
}

// ---------------------------------------------------------------------------
extern "C" void kernel_launch(void* const* d_in, const int* in_sizes, int n_in,
                              void* d_out, int out_size) {
    const float4* pts = (const float4*)d_in[0];
    const float*  W   = (const float*)d_in[1];
    float* out = (float*)d_out;
    int n = in_sizes[0] / 4;

    // k_zero first: the 335 MB store stream overlaps the tiny init/points
    // kernels (no dependency between them).
    int n4 = out_size / 4;                       // 20.97M uint4
    k_zero<<<148 * 8, 256>>>((uint4*)d_out, n4); // grid-stride, full-chip

    k_init<<<(MASK_QWORDS + 255) / 256, 256>>>(W);
    k_points<<<(n + 255) / 256, 256>>>(pts, n);

    k_conv<<<(n + 255) / 256, 256>>>(out);       // n threads >= active voxel count
}